// round 4
// baseline (speedup 1.0000x reference)
#include <cuda_runtime.h>

#define NHID 32

// Folded constants: per hidden unit j: 9 feature coefficients K (basis
// {1,c0,s0}x{1,c1,s1}, b1 folded into K00), then W2[j][0..1], pad.
__device__ float g_const[NHID * 12];

struct cpx { float x, y; };

__device__ __forceinline__ void apply1q(cpx* s, cpx m00, cpx m01, cpx m10, cpx m11, int wire)
{
    int st = 1 << (2 - wire);
    for (int i = 0; i < 8; i++) {
        if (i & st) continue;
        cpx a = s[i], b = s[i + st];
        cpx n0 = { m00.x*a.x - m00.y*a.y + m01.x*b.x - m01.y*b.y,
                   m00.x*a.y + m00.y*a.x + m01.x*b.y + m01.y*b.x };
        cpx n1 = { m10.x*a.x - m10.y*a.y + m11.x*b.x - m11.y*b.y,
                   m10.x*a.y + m10.y*a.x + m11.x*b.y + m11.y*b.x };
        s[i] = n0; s[i + st] = n1;
    }
}

__device__ __forceinline__ void applyCRX(cpx* s, float c, float sn, int ctrl, int tgt)
{
    int cs = 1 << (2 - ctrl), ts = 1 << (2 - tgt);
    for (int i = 0; i < 8; i++) {
        if (!(i & cs) || (i & ts)) continue;
        cpx a = s[i], b = s[i + ts];
        s[i]      = { c*a.x + sn*b.y, c*a.y - sn*b.x };
        s[i + ts] = { c*b.x + sn*a.y, c*b.y - sn*a.x };
    }
}

// 1 block, 32 threads. Lanes 0-3 build the 4 reachable columns of the fixed
// unitary (j-independent), share via smem; then every lane j folds its row.
__global__ void setup_kernel(const float* __restrict__ theta,
                             const float* __restrict__ W1,
                             const float* __restrict__ b1,
                             const float* __restrict__ W2)
{
    __shared__ cpx Vs[4][8];
    int tid = threadIdx.x;

    if (tid < 4) {
        cpx s[8];
        for (int i = 0; i < 8; i++) s[i] = {0.f, 0.f};
        s[tid * 2] = {1.f, 0.f};
        float c, sn;
        sincosf(0.5f * theta[0], &sn, &c);
        apply1q(s, {c,0.f},{0.f,-sn},{0.f,-sn},{c,0.f}, 0);     // RX w0
        sincosf(0.5f * theta[1], &sn, &c);
        apply1q(s, {c,0.f},{-sn,0.f},{sn,0.f},{c,0.f}, 1);      // RY w1
        sincosf(0.5f * theta[2], &sn, &c);
        apply1q(s, {c,-sn},{0.f,0.f},{0.f,0.f},{c,sn}, 2);      // RZ w2
        sincosf(0.5f * theta[3], &sn, &c);
        applyCRX(s, c, sn, 0, 1);                                // CRX(0,1)
        sincosf(0.5f * theta[4], &sn, &c);
        apply1q(s, {c,0.f},{-sn,0.f},{sn,0.f},{c,0.f}, 2);      // RY w2
        sincosf(0.5f * theta[5], &sn, &c);
        apply1q(s, {c,0.f},{0.f,-sn},{0.f,-sn},{c,0.f}, 1);     // RX w1
        sincosf(0.5f * theta[6], &sn, &c);
        applyCRX(s, c, sn, 1, 2);                                // CRX(1,2)
        sincosf(0.5f * theta[7], &sn, &c);
        apply1q(s, {c,-sn},{0.f,0.f},{0.f,0.f},{c,sn}, 0);      // RZ w0
        for (int k = 0; k < 8; k++)
            Vs[tid][k] = (tid >= 2) ? cpx{ s[k].y, -s[k].x } : s[k]; // * (-i)
    }
    __syncwarp();

    int j = tid;
    float M[4][4];
    for (int a = 0; a < 4; a++)
        for (int b = 0; b < 4; b++) {
            float m = 0.f;
            for (int k = 0; k < 8; k++)
                m += W1[k * NHID + j] * (Vs[a][k].x * Vs[b][k].x + Vs[a][k].y * Vs[b][k].y);
            M[a][b] = m;
        }

    const float R[2][2][3] = { { {0.5f, 0.5f, 0.f}, {0.f, 0.f, 0.5f} },
                               { {0.f, 0.f, 0.5f}, {0.5f, -0.5f, 0.f} } };
    float K[3][3] = { {0.f,0.f,0.f},{0.f,0.f,0.f},{0.f,0.f,0.f} };
    for (int a = 0; a < 4; a++)
        for (int b = 0; b < 4; b++) {
            int ia = a >> 1, ja = a & 1, ib = b >> 1, jb = b & 1;
            float Mab = M[a][b];
            for (int m = 0; m < 3; m++)
                for (int n = 0; n < 3; n++)
                    K[m][n] += Mab * R[ia][ib][m] * R[ja][jb][n];
        }
    K[0][0] += b1[j];

    for (int t = 0; t < 9; t++) g_const[j * 12 + t] = K[t / 3][t % 3];
    g_const[j * 12 + 9]  = W2[j * 2 + 0];
    g_const[j * 12 + 10] = W2[j * 2 + 1];
    g_const[j * 12 + 11] = 0.f;
}

// ---- packed f32x2 helpers (Blackwell FFMA2 path) ----
typedef unsigned long long u64;
__device__ __forceinline__ u64 pk2(float lo, float hi) {
    u64 r; asm("mov.b64 %0, {%1,%2};" : "=l"(r) : "f"(lo), "f"(hi)); return r;
}
__device__ __forceinline__ void upk2(u64 v, float& lo, float& hi) {
    asm("mov.b64 {%0,%1}, %2;" : "=f"(lo), "=f"(hi) : "l"(v));
}
__device__ __forceinline__ u64 ffma2(u64 a, u64 b, u64 c) {
    u64 d; asm("fma.rn.f32x2 %0, %1, %2, %3;" : "=l"(d) : "l"(a), "l"(b), "l"(c)); return d;
}
__device__ __forceinline__ u64 relu2(u64 v) {
    float lo, hi;
    upk2(v, lo, hi);
    return pk2(fmaxf(lo, 0.f), fmaxf(hi, 0.f));
}

#define SPT 8  // samples per thread (4 packed pairs) — amortize LDS over 2x FFMA2

__global__ void __launch_bounds__(256, 3)
qmlp_kernel(const float* __restrict__ x,
            const float* __restrict__ b2,
            float* __restrict__ out, int B)
{
    // Duplicated constant layout per j (24 floats = 6 x 16B); vec v holds
    // consts 2v,2v+1 duplicated:
    //   q0=(K00d,K01d) q1=(K02d,K10d) q2=(K11d,K12d)
    //   q3=(K20d,K21d) q4=(K22d,W20d) q5=(W21d,pad)
    __shared__ float sd[NHID * 24];
    for (int i = threadIdx.x; i < NHID * 24; i += blockDim.x)
        sd[i] = g_const[(i / 24) * 12 + (i % 24) / 2];
    __syncthreads();

    int t  = blockIdx.x * blockDim.x + threadIdx.x;
    long long s0 = (long long)t * SPT;
    if (s0 >= B) return;

    float bias0 = __ldg(&b2[0]);
    float bias1 = __ldg(&b2[1]);

    const ulonglong2* kp = reinterpret_cast<const ulonglong2*>(sd);

    if (s0 + SPT <= B) {
        // 8 samples: six coalesced LDG.128; x2 is a global phase (unused)
        float xs[24];
        const float4* xv = reinterpret_cast<const float4*>(x + s0 * 3);
        #pragma unroll
        for (int i = 0; i < 6; i++) {
            float4 v = xv[i];
            xs[i*4+0] = v.x; xs[i*4+1] = v.y; xs[i*4+2] = v.z; xs[i*4+3] = v.w;
        }

        float c0s[SPT], s0s[SPT], c1s[SPT], s1s[SPT];
        #pragma unroll
        for (int i = 0; i < SPT; i++) {
            __sincosf(xs[3*i],     &s0s[i], &c0s[i]);
            __sincosf(xs[3*i + 1], &s1s[i], &c1s[i]);
        }

        // 4 packed pairs: pair p = samples {2p, 2p+1}
        u64 C0[4], S0[4], C1[4], S1[4], O0[4], O1[4];
        u64 biasp0 = pk2(bias0, bias0), biasp1 = pk2(bias1, bias1);
        #pragma unroll
        for (int p = 0; p < 4; p++) {
            C0[p] = pk2(c0s[2*p], c0s[2*p+1]);
            S0[p] = pk2(s0s[2*p], s0s[2*p+1]);
            C1[p] = pk2(c1s[2*p], c1s[2*p+1]);
            S1[p] = pk2(s1s[2*p], s1s[2*p+1]);
            O0[p] = biasp0;
            O1[p] = biasp1;
        }

        #pragma unroll 2
        for (int j = 0; j < NHID; j++) {
            ulonglong2 q0 = kp[j*6+0], q1 = kp[j*6+1];
            ulonglong2 q2 = kp[j*6+2], q3 = kp[j*6+3];
            ulonglong2 q4 = kp[j*6+4], q5 = kp[j*6+5];

            #pragma unroll
            for (int p = 0; p < 4; p++) {
                // Horner: g = t0 + c0*t1 + s0*t2,  t_i = K_i0 + c1*K_i1 + s1*K_i2
                u64 t0 = ffma2(C1[p], q0.y, q0.x);
                t0 = ffma2(S1[p], q1.x, t0);
                u64 t1 = ffma2(C1[p], q2.x, q1.y);
                t1 = ffma2(S1[p], q2.y, t1);
                u64 t2 = ffma2(C1[p], q3.y, q3.x);
                t2 = ffma2(S1[p], q4.x, t2);
                u64 g = ffma2(C0[p], t1, t0);
                g = ffma2(S0[p], t2, g);
                u64 h = relu2(g);
                O0[p] = ffma2(h, q4.y, O0[p]);
                O1[p] = ffma2(h, q5.x, O1[p]);
            }
        }

        // out layout [s*2 + ch]; pair p holds samples {2p, 2p+1}
        float4* ov = reinterpret_cast<float4*>(out + s0 * 2);
        #pragma unroll
        for (int p = 0; p < 4; p++) {
            float a0, a1, bb0, bb1;
            upk2(O0[p], a0, bb0);   // ch0 of samples 2p, 2p+1
            upk2(O1[p], a1, bb1);   // ch1 of samples 2p, 2p+1
            float4 w = { a0, a1, bb0, bb1 };
            ov[p] = w;
        }
    } else {
        // generic scalar tail (unused when SPT | B)
        for (long long s = s0; s < B; s++) {
            float xx0 = x[s * 3], xx1 = x[s * 3 + 1];
            float cc0, ss0, cc1, ss1;
            __sincosf(xx0, &ss0, &cc0);
            __sincosf(xx1, &ss1, &cc1);
            float o0 = bias0, o1 = bias1;
            for (int j = 0; j < NHID; j++) {
                const float* K = &sd[j * 24];
                float t0 = K[0]  + K[2]*cc1  + K[4]*ss1;
                float t1 = K[6]  + K[8]*cc1  + K[10]*ss1;
                float t2 = K[12] + K[14]*cc1 + K[16]*ss1;
                float h = fmaxf(t0 + cc0*t1 + ss0*t2, 0.f);
                o0 += h * K[18];
                o1 += h * K[20];
            }
            out[s * 2]     = o0;
            out[s * 2 + 1] = o1;
        }
    }
}

extern "C" void kernel_launch(void* const* d_in, const int* in_sizes, int n_in,
                              void* d_out, int out_size)
{
    const float* x     = (const float*)d_in[0];
    const float* theta = (const float*)d_in[1];
    const float* W1    = (const float*)d_in[2];
    const float* b1    = (const float*)d_in[3];
    const float* W2    = (const float*)d_in[4];
    const float* b2    = (const float*)d_in[5];
    int B = in_sizes[0] / 3;

    setup_kernel<<<1, 32>>>(theta, W1, b1, W2);

    int nthreads = (B + SPT - 1) / SPT;
    int nblocks  = (nthreads + 255) / 256;
    qmlp_kernel<<<nblocks, 256>>>(x, b2, (float*)d_out, B);
}